// round 1
// baseline (speedup 1.0000x reference)
#include <cuda_runtime.h>
#include <math.h>

// ---------------------------------------------------------------------------
// RDHAgent forward, restructured:
//   pairs (i,j): only net s(j) needed; y bilinear in (h ⊗ feat') so the
//   j-sum is pre-accumulated into G[row=(b,a,i), net][650]; head-merge
//   (softmax(merger_w)) folded into the 650x64 reduced matrix Mred[net].
//   m_jki = sum_net G_net @ Mred_net, then fc1/fc2 epilogue.
// ---------------------------------------------------------------------------

#define NBA   384          // BS*NA rows
#define EM1_  8
#define KNET  650          // 65*10 (hh[65] x feat'[10])
#define KPAD  672          // padded to multiple of 32
#define KTOT  (3*KPAD)     // 2016: 3 nets concatenated along K
#define NROWS (NBA*EM1_)   // 3072

__device__ float g_G[NROWS * KTOT];        // ~24.8 MB scratch
__device__ float g_Mred[3 * KPAD * 64];    // reduced hyper-matrices
__device__ float g_Y[NROWS * 64];          // m_jki

// ---------------- K0: build Mred[net][K][dh] ----------------
// M[j*10+k][d] = W2[j][k*256+d] (j<64) or b2[k*256+d] (j==64), d = h*64+dh.
// Fold softmax(merger_w) over heads: Mred[K][dh] = sum_h mw[h,dh]*M[K][h*64+dh]
__global__ void k_mred(const float* __restrict__ wA2, const float* __restrict__ bA2,
                       const float* __restrict__ wE2, const float* __restrict__ bE2,
                       const float* __restrict__ wL2, const float* __restrict__ bL2,
                       const float* __restrict__ mergw) {
    int K = blockIdx.x, net = blockIdx.y, dh = threadIdx.x;
    float outv = 0.f;
    if (K < KNET) {
        float m0 = mergw[dh], m1 = mergw[64+dh], m2 = mergw[128+dh], m3 = mergw[192+dh];
        float mx = fmaxf(fmaxf(m0,m1), fmaxf(m2,m3));
        float e0 = expf(m0-mx), e1 = expf(m1-mx), e2 = expf(m2-mx), e3 = expf(m3-mx);
        float inv = 1.f/(e0+e1+e2+e3);
        int j10 = K/10;
        int k   = K - j10*10;
        const float* w2 = (net==0)?wA2:((net==1)?wE2:wL2);
        const float* b2 = (net==0)?bA2:((net==1)?bE2:bL2);
        const float* src = (j10 < 64) ? (w2 + j10*2560) : b2;
        int base = k*256 + dh;
        outv = (e0*src[base] + e1*src[base+64] + e2*src[base+128] + e3*src[base+192]) * inv;
    }
    g_Mred[(net*KPAD + K)*64 + dh] = outv;
}

// ---------------- K1: features + h + G accumulation ----------------
// One block per (b,a). Warp w owns i=w; loops j=0..7 (net fixed per j),
// accumulates G in registers (21 entries/lane x 3 nets).
__global__ void __launch_bounds__(256) k_feat_g(
    const float* __restrict__ obs,
    const float* __restrict__ wA1, const float* __restrict__ bA1,
    const float* __restrict__ wE1, const float* __restrict__ bE1,
    const float* __restrict__ wL1, const float* __restrict__ bL1)
{
    __shared__ float s_w1[3][576];
    __shared__ float s_b1[3][64];
    __shared__ float s_velx[8], s_vely[8], s_sint[8], s_cost[8], s_sina[8], s_cosa[8];
    __shared__ float s_rbf[8][3];
    __shared__ float s_h[8][66];     // hh per warp (65 used)
    __shared__ float s_feat[8][10];  // feat' per warp

    int tid = threadIdx.x, ba = blockIdx.x;
    int w = tid >> 5, l = tid & 31;

    for (int idx = tid; idx < 576; idx += 256) {
        s_w1[0][idx] = wA1[idx]; s_w1[1][idx] = wE1[idx]; s_w1[2][idx] = wL1[idx];
    }
    if (tid < 64) { s_b1[0][tid]=bA1[tid]; s_b1[1][tid]=bE1[tid]; s_b1[2][tid]=bL1[tid]; }

    const float* ob = obs + ba*30;
    if (tid < 8) {
        int j = tid; float px,py,vx,vy;
        if (j < 2)      { px=ob[10+2*j];     py=ob[11+2*j];     vx=ob[20+2*j];     vy=ob[21+2*j]; }
        else if (j < 5) { px=ob[14+2*(j-2)]; py=ob[15+2*(j-2)]; vx=ob[24+2*(j-2)]; vy=ob[25+2*(j-2)]; }
        else            { px=ob[4+2*(j-5)];  py=ob[5+2*(j-5)];  vx=-ob[0];         vy=-ob[1]; }
        float dist = sqrtf(px*px+py*py);
        float id = 1.f/(dist+1e-7f);
        s_sint[j]=py*id; s_cost[j]=px*id;
        float vn = sqrtf(vx*vx+vy*vy);
        float iv = 1.f/(vn+1e-7f);
        s_sina[j]=vy*iv; s_cosa[j]=vx*iv;
        s_velx[j]=vx; s_vely[j]=vy;
        s_rbf[j][0]=expf(-0.02f*dist*dist);
        float d1=dist-5.f;  s_rbf[j][1]=expf(-0.02f*d1*d1);
        float d2=dist-10.f; s_rbf[j][2]=expf(-0.02f*d2*d2);
    }
    __syncthreads();

    const int i = w;
    float acc[3][21];
    #pragma unroll
    for (int n=0;n<3;n++)
        #pragma unroll
        for (int u=0;u<21;u++) acc[n][u]=0.f;

    #pragma unroll
    for (int j=0;j<8;j++){
        const int net = (j<2)?0:((j<5)?1:2);
        if (l < 10) {
            float v;
            if      (l==0) v=s_rbf[j][0];
            else if (l==1) v=s_rbf[j][1];
            else if (l==2) v=s_rbf[j][2];
            else if (l==3) v=s_sint[j]*s_cost[i]-s_cost[j]*s_sint[i];
            else if (l==4) v=s_cost[j]*s_cost[i]+s_sint[j]*s_sint[i];
            else if (l==5) v=s_sina[j]*s_cost[i]-s_cosa[j]*s_sint[i];
            else if (l==6) v=s_cosa[j]*s_cost[i]+s_sina[j]*s_sint[i];
            else if (l==7) v=s_velx[j]-s_velx[i];
            else if (l==8) v=s_vely[j]-s_vely[i];
            else           v=1.f;
            s_feat[w][l]=v;
        }
        __syncwarp();
        float f[9];
        #pragma unroll
        for (int k=0;k<9;k++) f[k]=s_feat[w][k];
        {
            const float* w1 = s_w1[net];
            const float* b1 = s_b1[net];
            #pragma unroll
            for (int t2=0;t2<2;t2++){
                int m = 2*l+t2;
                float hv = b1[m];
                #pragma unroll
                for (int k=0;k<9;k++) hv = fmaf(f[k], w1[k*64+m], hv);
                s_h[w][m] = (hv>0.f)? hv : 0.01f*hv;   // leaky_relu(0.01)
            }
        }
        if (l==0) s_h[w][64]=1.f;
        __syncwarp();
        #pragma unroll
        for (int u=0;u<21;u++){
            int K = u*32+l;
            if (K < KNET){
                int j10 = K/10;
                int k   = K - j10*10;
                acc[net][u] = fmaf(s_h[w][j10], s_feat[w][k], acc[net][u]);
            }
        }
        __syncwarp();
    }

    int rowbase = (ba*8+w)*KTOT;
    #pragma unroll
    for (int n=0;n<3;n++)
        #pragma unroll
        for (int u=0;u<21;u++){
            int K = u*32+l;
            g_G[rowbase + n*KPAD + K] = (K<KNET)? acc[n][u] : 0.f;
        }
}

// ---------------- K2: Y = G @ Mred  (3072 x 2016 x 64) ----------------
// 16 rows x 64 cols per block; K chunks of 32 through shared.
__global__ void __launch_bounds__(256) k_gemm() {
    __shared__ float Gs[16][33];
    __shared__ float Ms[32][64];
    int t   = threadIdx.x;
    int rb  = blockIdx.x*16;
    int row = t>>4;
    int c4  = (t&15)*4;
    float a0=0.f,a1=0.f,a2=0.f,a3=0.f;
    for (int k0=0;k0<KTOT;k0+=32){
        #pragma unroll
        for (int it=0;it<2;it++){
            int idx = t + it*256;
            Gs[idx>>5][idx&31] = g_G[(rb + (idx>>5))*KTOT + k0 + (idx&31)];
        }
        const float* msrc = g_Mred + k0*64;
        #pragma unroll
        for (int it=0;it<8;it++){
            int idx = t + it*256;
            (&Ms[0][0])[idx] = msrc[idx];
        }
        __syncthreads();
        #pragma unroll
        for (int kk=0;kk<32;kk++){
            float av = Gs[row][kk];
            float4 m = *reinterpret_cast<const float4*>(&Ms[kk][c4]);
            a0=fmaf(av,m.x,a0); a1=fmaf(av,m.y,a1); a2=fmaf(av,m.z,a2); a3=fmaf(av,m.w,a3);
        }
        __syncthreads();
    }
    float4 o; o.x=a0; o.y=a1; o.z=a2; o.w=a3;
    *reinterpret_cast<float4*>(&g_Y[(rb+row)*64 + c4]) = o;
}

// ---------------- K3: epilogue (final concat, fc1, fc2, mean) ----------------
__global__ void __launch_bounds__(64) k_final(
    const float* __restrict__ obs, const float* __restrict__ acts,
    const float* __restrict__ fc1w, const float* __restrict__ fc1b,
    const float* __restrict__ fc2w, const float* __restrict__ fc2b,
    float* __restrict__ out)
{
    __shared__ float s_fc1[67*64];
    __shared__ float s_sint[8], s_cost[8];
    __shared__ float s_x1[68];
    __shared__ float s_red[64];
    __shared__ float s_act[3]; // act_norm, sin_b, cos_b
    int tid = threadIdx.x, ba = blockIdx.x;

    for (int idx = tid; idx < 67*64; idx += 64) s_fc1[idx] = fc1w[idx];

    const float* ob = obs + ba*30;
    if (tid < 8) {
        int j = tid; float px,py;
        if (j < 2)      { px=ob[10+2*j];     py=ob[11+2*j];     }
        else if (j < 5) { px=ob[14+2*(j-2)]; py=ob[15+2*(j-2)]; }
        else            { px=ob[4+2*(j-5)];  py=ob[5+2*(j-5)];  }
        float dist = sqrtf(px*px+py*py);
        float id = 1.f/(dist+1e-7f);
        s_sint[j]=py*id; s_cost[j]=px*id;
    }
    if (tid == 8) {
        float ax = acts[ba*2], ay = acts[ba*2+1];
        float an = sqrtf(ax*ax+ay*ay);
        s_act[0]=an; s_act[1]=ay/(an+1e-7f); s_act[2]=ax/(an+1e-7f);
    }
    __syncthreads();

    float fb = fc1b[tid];
    float w2v = fc2w[tid];
    float qsum = 0.f;

    for (int i=0;i<8;i++){
        float m = g_Y[(ba*8+i)*64 + tid];
        s_x1[tid] = fmaxf(m, 0.f);
        if (tid == 0){
            s_x1[64] = fmaxf(s_act[0], 0.f);
            float aa0 = s_act[1]*s_cost[i]-s_act[2]*s_sint[i];
            float aa1 = s_act[2]*s_cost[i]+s_act[1]*s_sint[i];
            s_x1[65] = fmaxf(aa0, 0.f);
            s_x1[66] = fmaxf(aa1, 0.f);
        }
        __syncthreads();
        float v = fb;
        #pragma unroll
        for (int c=0;c<67;c++) v = fmaf(s_x1[c], s_fc1[c*64+tid], v);
        v = fmaxf(v, 0.f);
        out[NBA + (ba*8+i)*64 + tid] = v;   // x output
        s_red[tid] = v*w2v;
        __syncthreads();
        if (tid == 0){
            float s = 0.f;
            for (int c=0;c<64;c++) s += s_red[c];
            qsum += s;
        }
        __syncthreads();
    }
    if (tid == 0) out[ba] = qsum*(1.f/8.f) + fc2b[0];   // q output
}

// ---------------- launch ----------------
extern "C" void kernel_launch(void* const* d_in, const int* in_sizes, int n_in,
                              void* d_out, int out_size) {
    const float* inputs = (const float*)d_in[0];
    // d_in[1] = hidden_state (unused by reference)
    const float* actions = (const float*)d_in[2];
    const float* hA1w=(const float*)d_in[3],  *hA1b=(const float*)d_in[4];
    const float* hA2w=(const float*)d_in[5],  *hA2b=(const float*)d_in[6];
    const float* hE1w=(const float*)d_in[7],  *hE1b=(const float*)d_in[8];
    const float* hE2w=(const float*)d_in[9],  *hE2b=(const float*)d_in[10];
    const float* hL1w=(const float*)d_in[11], *hL1b=(const float*)d_in[12];
    const float* hL2w=(const float*)d_in[13], *hL2b=(const float*)d_in[14];
    const float* mergw=(const float*)d_in[15];
    const float* fc1w=(const float*)d_in[16], *fc1b=(const float*)d_in[17];
    const float* fc2w=(const float*)d_in[18], *fc2b=(const float*)d_in[19];
    float* out = (float*)d_out;

    dim3 g0(KPAD, 3);
    k_mred<<<g0, 64>>>(hA2w,hA2b,hE2w,hE2b,hL2w,hL2b,mergw);
    k_feat_g<<<NBA, 256>>>(inputs, hA1w,hA1b,hE1w,hE1b,hL1w,hL1b);
    k_gemm<<<NROWS/16, 256>>>();
    k_final<<<NBA, 64>>>(inputs, actions, fc1w, fc1b, fc2w, fc2b, out);
}

// round 3
// speedup vs baseline: 1.6482x; 1.6482x over previous
#include <cuda_runtime.h>
#include <math.h>

// ---------------------------------------------------------------------------
// RDHAgent forward, restructured (see R1 notes). R3 = R2 with k_final fixed
// for its 256-thread launch (warp w <-> entity i=w) + aligned shared tiles.
// ---------------------------------------------------------------------------

#define NBA   384          // BS*NA rows
#define EM1_  8
#define KNET  650          // 65*10 (hh[65] x feat'[10])
#define KPAD  672          // padded to multiple of 32
#define KTOT  (3*KPAD)     // 2016
#define NROWS (NBA*EM1_)   // 3072

__device__ float g_G[NROWS * KTOT];        // ~24.8 MB scratch
__device__ float g_Mred[3 * KPAD * 64];    // reduced hyper-matrices
__device__ float g_Yp[3 * NROWS * 64];     // per-net partial m_jki

// ---------------- K0: build Mred[net][K][dh] ----------------
__global__ void k_mred(const float* __restrict__ wA2, const float* __restrict__ bA2,
                       const float* __restrict__ wE2, const float* __restrict__ bE2,
                       const float* __restrict__ wL2, const float* __restrict__ bL2,
                       const float* __restrict__ mergw) {
    int K = blockIdx.x, net = blockIdx.y, dh = threadIdx.x;
    float outv = 0.f;
    if (K < KNET) {
        float m0 = mergw[dh], m1 = mergw[64+dh], m2 = mergw[128+dh], m3 = mergw[192+dh];
        float mx = fmaxf(fmaxf(m0,m1), fmaxf(m2,m3));
        float e0 = expf(m0-mx), e1 = expf(m1-mx), e2 = expf(m2-mx), e3 = expf(m3-mx);
        float inv = 1.f/(e0+e1+e2+e3);
        int j10 = K/10;
        int k   = K - j10*10;
        const float* w2 = (net==0)?wA2:((net==1)?wE2:wL2);
        const float* b2 = (net==0)?bA2:((net==1)?bE2:bL2);
        const float* src = (j10 < 64) ? (w2 + j10*2560) : b2;
        int base = k*256 + dh;
        outv = (e0*src[base] + e1*src[base+64] + e2*src[base+128] + e3*src[base+192]) * inv;
    }
    g_Mred[(net*KPAD + K)*64 + dh] = outv;
}

// ---------------- K1: features + h + G accumulation ----------------
__global__ void __launch_bounds__(256) k_feat_g(
    const float* __restrict__ obs,
    const float* __restrict__ wA1, const float* __restrict__ bA1,
    const float* __restrict__ wE1, const float* __restrict__ bE1,
    const float* __restrict__ wL1, const float* __restrict__ bL1)
{
    __shared__ float s_w1[3][576];
    __shared__ float s_b1[3][64];
    __shared__ float s_velx[8], s_vely[8], s_sint[8], s_cost[8], s_sina[8], s_cosa[8];
    __shared__ float s_rbf[8][3];
    __shared__ float s_h[8][66];
    __shared__ float s_feat[8][10];

    int tid = threadIdx.x, ba = blockIdx.x;
    int w = tid >> 5, l = tid & 31;

    for (int idx = tid; idx < 576; idx += 256) {
        s_w1[0][idx] = wA1[idx]; s_w1[1][idx] = wE1[idx]; s_w1[2][idx] = wL1[idx];
    }
    if (tid < 64) { s_b1[0][tid]=bA1[tid]; s_b1[1][tid]=bE1[tid]; s_b1[2][tid]=bL1[tid]; }

    const float* ob = obs + ba*30;
    if (tid < 8) {
        int j = tid; float px,py,vx,vy;
        if (j < 2)      { px=ob[10+2*j];     py=ob[11+2*j];     vx=ob[20+2*j];     vy=ob[21+2*j]; }
        else if (j < 5) { px=ob[14+2*(j-2)]; py=ob[15+2*(j-2)]; vx=ob[24+2*(j-2)]; vy=ob[25+2*(j-2)]; }
        else            { px=ob[4+2*(j-5)];  py=ob[5+2*(j-5)];  vx=-ob[0];         vy=-ob[1]; }
        float dist = sqrtf(px*px+py*py);
        float id = 1.f/(dist+1e-7f);
        s_sint[j]=py*id; s_cost[j]=px*id;
        float vn = sqrtf(vx*vx+vy*vy);
        float iv = 1.f/(vn+1e-7f);
        s_sina[j]=vy*iv; s_cosa[j]=vx*iv;
        s_velx[j]=vx; s_vely[j]=vy;
        s_rbf[j][0]=expf(-0.02f*dist*dist);
        float d1=dist-5.f;  s_rbf[j][1]=expf(-0.02f*d1*d1);
        float d2=dist-10.f; s_rbf[j][2]=expf(-0.02f*d2*d2);
    }
    __syncthreads();

    const int i = w;
    float acc[3][21];
    #pragma unroll
    for (int n=0;n<3;n++)
        #pragma unroll
        for (int u=0;u<21;u++) acc[n][u]=0.f;

    #pragma unroll
    for (int j=0;j<8;j++){
        const int net = (j<2)?0:((j<5)?1:2);
        if (l < 10) {
            float v;
            if      (l==0) v=s_rbf[j][0];
            else if (l==1) v=s_rbf[j][1];
            else if (l==2) v=s_rbf[j][2];
            else if (l==3) v=s_sint[j]*s_cost[i]-s_cost[j]*s_sint[i];
            else if (l==4) v=s_cost[j]*s_cost[i]+s_sint[j]*s_sint[i];
            else if (l==5) v=s_sina[j]*s_cost[i]-s_cosa[j]*s_sint[i];
            else if (l==6) v=s_cosa[j]*s_cost[i]+s_sina[j]*s_sint[i];
            else if (l==7) v=s_velx[j]-s_velx[i];
            else if (l==8) v=s_vely[j]-s_vely[i];
            else           v=1.f;
            s_feat[w][l]=v;
        }
        __syncwarp();
        float f[9];
        #pragma unroll
        for (int k=0;k<9;k++) f[k]=s_feat[w][k];
        {
            const float* w1 = s_w1[net];
            const float* b1 = s_b1[net];
            #pragma unroll
            for (int t2=0;t2<2;t2++){
                int m = 2*l+t2;
                float hv = b1[m];
                #pragma unroll
                for (int k=0;k<9;k++) hv = fmaf(f[k], w1[k*64+m], hv);
                s_h[w][m] = (hv>0.f)? hv : 0.01f*hv;
            }
        }
        if (l==0) s_h[w][64]=1.f;
        __syncwarp();
        #pragma unroll
        for (int u=0;u<21;u++){
            int K = u*32+l;
            if (K < KNET){
                int j10 = K/10;
                int k   = K - j10*10;
                acc[net][u] = fmaf(s_h[w][j10], s_feat[w][k], acc[net][u]);
            }
        }
        __syncwarp();
    }

    int rowbase = (ba*8+w)*KTOT;
    #pragma unroll
    for (int n=0;n<3;n++)
        #pragma unroll
        for (int u=0;u<21;u++){
            int K = u*32+l;
            g_G[rowbase + n*KPAD + K] = (K<KNET)? acc[n][u] : 0.f;
        }
}

// ---------------- K2: Yp[net] = G[:,net] @ Mred[net] ----------------
// grid (192, 3), block 128. Tile: 16 rows x 64 cols; thread: 2 rows x 4 cols.
__global__ void __launch_bounds__(128) k_gemm() {
    __shared__ __align__(16) float Gs[16][33];
    __shared__ __align__(16) float Ms[32][64];
    int tile = blockIdx.x, net = blockIdx.y;
    int t  = threadIdx.x;
    int ty = t >> 4;        // 0..7
    int tx = t & 15;        // 0..15
    int rb = tile*16;
    int kbase = net*KPAD;

    float a00=0.f,a01=0.f,a02=0.f,a03=0.f;
    float a10=0.f,a11=0.f,a12=0.f,a13=0.f;

    for (int k0=0; k0<KPAD; k0+=32){
        #pragma unroll
        for (int it=0; it<4; it++){
            int idx = t + it*128;                 // 0..511
            Gs[idx>>5][idx&31] = g_G[(rb + (idx>>5))*KTOT + kbase + k0 + (idx&31)];
        }
        const float* msrc = g_Mred + (kbase + k0)*64;
        #pragma unroll
        for (int it=0; it<16; it++){
            int idx = t + it*128;                 // 0..2047
            (&Ms[0][0])[idx] = msrc[idx];
        }
        __syncthreads();
        #pragma unroll
        for (int kk=0; kk<32; kk++){
            float g0 = Gs[ty][kk];
            float g1 = Gs[ty+8][kk];
            float4 m = *reinterpret_cast<const float4*>(&Ms[kk][tx*4]);
            a00=fmaf(g0,m.x,a00); a01=fmaf(g0,m.y,a01); a02=fmaf(g0,m.z,a02); a03=fmaf(g0,m.w,a03);
            a10=fmaf(g1,m.x,a10); a11=fmaf(g1,m.y,a11); a12=fmaf(g1,m.z,a12); a13=fmaf(g1,m.w,a13);
        }
        __syncthreads();
    }
    float4 o0; o0.x=a00; o0.y=a01; o0.z=a02; o0.w=a03;
    float4 o1; o1.x=a10; o1.y=a11; o1.z=a12; o1.w=a13;
    *reinterpret_cast<float4*>(&g_Yp[(net*NROWS + rb + ty)*64 + tx*4])     = o0;
    *reinterpret_cast<float4*>(&g_Yp[(net*NROWS + rb + ty + 8)*64 + tx*4]) = o1;
}

// ---------------- K3: epilogue ----------------
// 256 threads per ba = 8 warps; warp w handles entity i = w.
__global__ void __launch_bounds__(256) k_final(
    const float* __restrict__ obs, const float* __restrict__ acts,
    const float* __restrict__ fc1w, const float* __restrict__ fc1b,
    const float* __restrict__ fc2w, const float* __restrict__ fc2b,
    float* __restrict__ out)
{
    __shared__ float s_fc1[67*64];
    __shared__ float s_x1[8][68];
    __shared__ float s_sint[8], s_cost[8];
    __shared__ float s_act[3];
    __shared__ float s_qw[8];
    int tid = threadIdx.x, ba = blockIdx.x;
    int w = tid >> 5, l = tid & 31;

    for (int idx = tid; idx < 67*64; idx += 256) s_fc1[idx] = fc1w[idx];

    const float* ob = obs + ba*30;
    if (tid < 8) {
        int j = tid; float px,py;
        if (j < 2)      { px=ob[10+2*j];     py=ob[11+2*j];     }
        else if (j < 5) { px=ob[14+2*(j-2)]; py=ob[15+2*(j-2)]; }
        else            { px=ob[4+2*(j-5)];  py=ob[5+2*(j-5)];  }
        float dist = sqrtf(px*px+py*py);
        float id = 1.f/(dist+1e-7f);
        s_sint[j]=py*id; s_cost[j]=px*id;
    }
    if (tid == 8) {
        float ax = acts[ba*2], ay = acts[ba*2+1];
        float an = sqrtf(ax*ax+ay*ay);
        s_act[0]=an; s_act[1]=ay/(an+1e-7f); s_act[2]=ax/(an+1e-7f);
    }
    __syncthreads();

    const int i = w;
    const int row = ba*8 + i;
    float m0 = g_Yp[row*64+l]
             + g_Yp[(NROWS+row)*64+l]
             + g_Yp[(2*NROWS+row)*64+l];
    float m1 = g_Yp[row*64+l+32]
             + g_Yp[(NROWS+row)*64+l+32]
             + g_Yp[(2*NROWS+row)*64+l+32];
    s_x1[w][l]    = fmaxf(m0, 0.f);
    s_x1[w][l+32] = fmaxf(m1, 0.f);
    if (l == 0){
        s_x1[w][64] = fmaxf(s_act[0], 0.f);
        float aa0 = s_act[1]*s_cost[i] - s_act[2]*s_sint[i];
        float aa1 = s_act[2]*s_cost[i] + s_act[1]*s_sint[i];
        s_x1[w][65] = fmaxf(aa0, 0.f);
        s_x1[w][66] = fmaxf(aa1, 0.f);
    }
    __syncwarp();

    float v0 = fc1b[l], v1 = fc1b[l+32];
    #pragma unroll
    for (int c=0; c<67; c++){
        float xv = s_x1[w][c];
        v0 = fmaf(xv, s_fc1[c*64 + l],      v0);
        v1 = fmaf(xv, s_fc1[c*64 + l + 32], v1);
    }
    v0 = fmaxf(v0, 0.f);
    v1 = fmaxf(v1, 0.f);
    out[NBA + row*64 + l]      = v0;
    out[NBA + row*64 + l + 32] = v1;

    float qp = v0*fc2w[l] + v1*fc2w[l+32];
    #pragma unroll
    for (int off=16; off; off>>=1) qp += __shfl_down_sync(0xffffffffu, qp, off);
    if (l == 0) s_qw[w] = qp;
    __syncthreads();
    if (tid == 0){
        float s = 0.f;
        #pragma unroll
        for (int k=0;k<8;k++) s += s_qw[k];
        out[ba] = s*0.125f + fc2b[0];
    }
}

// ---------------- launch ----------------
extern "C" void kernel_launch(void* const* d_in, const int* in_sizes, int n_in,
                              void* d_out, int out_size) {
    const float* inputs = (const float*)d_in[0];
    const float* actions = (const float*)d_in[2];
    const float* hA1w=(const float*)d_in[3],  *hA1b=(const float*)d_in[4];
    const float* hA2w=(const float*)d_in[5],  *hA2b=(const float*)d_in[6];
    const float* hE1w=(const float*)d_in[7],  *hE1b=(const float*)d_in[8];
    const float* hE2w=(const float*)d_in[9],  *hE2b=(const float*)d_in[10];
    const float* hL1w=(const float*)d_in[11], *hL1b=(const float*)d_in[12];
    const float* hL2w=(const float*)d_in[13], *hL2b=(const float*)d_in[14];
    const float* mergw=(const float*)d_in[15];
    const float* fc1w=(const float*)d_in[16], *fc1b=(const float*)d_in[17];
    const float* fc2w=(const float*)d_in[18], *fc2b=(const float*)d_in[19];
    float* out = (float*)d_out;

    dim3 g0(KPAD, 3);
    k_mred<<<g0, 64>>>(hA2w,hA2b,hE2w,hE2b,hL2w,hL2b,mergw);
    k_feat_g<<<NBA, 256>>>(inputs, hA1w,hA1b,hE1w,hE1b,hL1w,hL1b);
    dim3 g2(NROWS/16, 3);
    k_gemm<<<g2, 128>>>();
    k_final<<<NBA, 256>>>(inputs, actions, fc1w, fc1b, fc2w, fc2b, out);
}

// round 4
// speedup vs baseline: 1.9476x; 1.1816x over previous
#include <cuda_runtime.h>
#include <math.h>

// ---------------------------------------------------------------------------
// RDHAgent forward. R4: two kernels.
//   k_mred: fold softmax(merger_w) + reindex W2/b2 -> Mred[net][672][64]
//   k_fused: per block (2 ba = 16 rows): build G per net in shared,
//            GEMM vs Mred accumulating across nets in registers,
//            then fc1/fc2 epilogue. No global G scratch.
// ---------------------------------------------------------------------------

#define NBA   384
#define KNET  650
#define KPAD  672
#define NROWS (NBA*8)

__device__ float g_Mred[3 * KPAD * 64];

// ---------------- K0: build Mred[net][K][dh] ----------------
__global__ void k_mred(const float* __restrict__ wA2, const float* __restrict__ bA2,
                       const float* __restrict__ wE2, const float* __restrict__ bE2,
                       const float* __restrict__ wL2, const float* __restrict__ bL2,
                       const float* __restrict__ mergw) {
    int K = blockIdx.x, net = blockIdx.y, dh = threadIdx.x;
    float outv = 0.f;
    if (K < KNET) {
        float m0 = mergw[dh], m1 = mergw[64+dh], m2 = mergw[128+dh], m3 = mergw[192+dh];
        float mx = fmaxf(fmaxf(m0,m1), fmaxf(m2,m3));
        float e0 = expf(m0-mx), e1 = expf(m1-mx), e2 = expf(m2-mx), e3 = expf(m3-mx);
        float inv = 1.f/(e0+e1+e2+e3);
        int j10 = K/10;
        int k   = K - j10*10;
        const float* w2 = (net==0)?wA2:((net==1)?wE2:wL2);
        const float* b2 = (net==0)?bA2:((net==1)?bE2:bL2);
        const float* src = (j10 < 64) ? (w2 + j10*2560) : b2;
        int base = k*256 + dh;
        outv = (e0*src[base] + e1*src[base+64] + e2*src[base+128] + e3*src[base+192]) * inv;
    }
    g_Mred[(net*KPAD + K)*64 + dh] = outv;
}

// ---------------- K1: fused feat + G + GEMM + epilogue ----------------
// grid 192, block 128. Block handles ba0 = 2*blockIdx, ba0+1 (16 rows).
// Shared layout (floats):
//   Gs   [16][672]      10752   (reused as sX[16][68] in epilogue)
//   Ms   [32][64]        2048
//   sF   fc1w [67][64]   4288
//   sW1  [3][576]        1728
//   sB1  [3][64]          192
//   sFeat[2][8][8][10]   1280
//   scalars               ~176
__global__ void __launch_bounds__(128) k_fused(
    const float* __restrict__ obs, const float* __restrict__ acts,
    const float* __restrict__ wA1, const float* __restrict__ bA1,
    const float* __restrict__ wE1, const float* __restrict__ bE1,
    const float* __restrict__ wL1, const float* __restrict__ bL1,
    const float* __restrict__ fc1w, const float* __restrict__ fc1b,
    const float* __restrict__ fc2w, const float* __restrict__ fc2b,
    float* __restrict__ out)
{
    extern __shared__ float sm[];
    float* Gs    = sm;                   // 10752
    float* Ms    = Gs + 16*KPAD;         // 2048
    float* sF    = Ms + 32*64;           // 4288
    float* sW1   = sF + 67*64;           // 1728
    float* sB1   = sW1 + 3*576;          // 192
    float* sFeat = sB1 + 3*64;           // 1280
    float* sS    = sFeat + 1280;         // scalar block
    // scalar sub-layout
    float* s_velx = sS;          // [2][8]
    float* s_vely = sS + 16;
    float* s_sint = sS + 32;
    float* s_cost = sS + 48;
    float* s_sina = sS + 64;
    float* s_cosa = sS + 80;
    float* s_rbf  = sS + 96;     // [2][8][3]
    float* s_act  = sS + 144;    // [2][3]
    float* s_q    = sS + 152;    // [16]

    const int t  = threadIdx.x;
    const int ba0 = blockIdx.x * 2;

    // ---- stage weights ----
    for (int idx = t; idx < 576; idx += 128) {
        sW1[idx] = wA1[idx]; sW1[576+idx] = wE1[idx]; sW1[1152+idx] = wL1[idx];
    }
    for (int idx = t; idx < 64; idx += 128) {
        sB1[idx] = bA1[idx]; sB1[64+idx] = bE1[idx]; sB1[128+idx] = bL1[idx];
    }
    {
        const float4* f4 = (const float4*)fc1w;
        float4* d4 = (float4*)sF;
        for (int idx = t; idx < 67*16; idx += 128) d4[idx] = f4[idx];
    }

    // ---- per-(ba,entity) scalars ----
    if (t < 16) {
        int bl = t >> 3, j = t & 7;
        const float* ob = obs + (ba0 + bl)*30;
        float px,py,vx,vy;
        if (j < 2)      { px=ob[10+2*j];     py=ob[11+2*j];     vx=ob[20+2*j];     vy=ob[21+2*j]; }
        else if (j < 5) { px=ob[14+2*(j-2)]; py=ob[15+2*(j-2)]; vx=ob[24+2*(j-2)]; vy=ob[25+2*(j-2)]; }
        else            { px=ob[4+2*(j-5)];  py=ob[5+2*(j-5)];  vx=-ob[0];         vy=-ob[1]; }
        float dist = sqrtf(px*px+py*py);
        float id = 1.f/(dist+1e-7f);
        s_sint[t]=py*id; s_cost[t]=px*id;
        float vn = sqrtf(vx*vx+vy*vy);
        float iv = 1.f/(vn+1e-7f);
        s_sina[t]=vy*iv; s_cosa[t]=vx*iv;
        s_velx[t]=vx; s_vely[t]=vy;
        s_rbf[t*3+0]=expf(-0.02f*dist*dist);
        float d1=dist-5.f;  s_rbf[t*3+1]=expf(-0.02f*d1*d1);
        float d2=dist-10.f; s_rbf[t*3+2]=expf(-0.02f*d2*d2);
    } else if (t < 18) {
        int bl = t - 16;
        float ax = acts[(ba0+bl)*2], ay = acts[(ba0+bl)*2+1];
        float an = sqrtf(ax*ax+ay*ay);
        s_act[bl*3+0]=an; s_act[bl*3+1]=ay/(an+1e-7f); s_act[bl*3+2]=ax/(an+1e-7f);
    }
    __syncthreads();

    // ---- precompute feat'[10] per (bl, i, j) : thread t <-> (bl,i,j) ----
    {
        int bl = t >> 6, i = (t >> 3) & 7, j = t & 7;
        int oI = bl*8 + i, oJ = bl*8 + j;
        float* fd = sFeat + t*10;
        fd[0] = s_rbf[oJ*3+0];
        fd[1] = s_rbf[oJ*3+1];
        fd[2] = s_rbf[oJ*3+2];
        float si=s_sint[oI], ci=s_cost[oI], sj=s_sint[oJ], cj=s_cost[oJ];
        float sa=s_sina[oJ], ca=s_cosa[oJ];
        fd[3] = sj*ci - cj*si;
        fd[4] = cj*ci + sj*si;
        fd[5] = sa*ci - ca*si;
        fd[6] = ca*ci + sa*si;
        fd[7] = s_velx[oJ]-s_velx[oI];
        fd[8] = s_vely[oJ]-s_vely[oI];
        fd[9] = 1.f;
    }
    __syncthreads();

    // ---- per-thread GEMM accumulators: rows ty, ty+8; cols tx*4..+3 ----
    const int tx = t & 15, ty = t >> 4;
    float a00=0.f,a01=0.f,a02=0.f,a03=0.f;
    float a10=0.f,a11=0.f,a12=0.f,a13=0.f;

    const int w = t >> 5, l = t & 31;     // build-phase warp/lane
    const int jb[3] = {0,2,5}, je[3] = {2,5,8};

    for (int net = 0; net < 3; net++) {
        // ---- build Gs[16][672] for this net ----
        const float* w1 = sW1 + net*576;
        const float* b1 = sB1 + net*64;
        #pragma unroll
        for (int r4 = 0; r4 < 4; r4++) {
            int r  = w + r4*4;            // row 0..15
            int bl = r >> 3, i = r & 7;
            float acc0[10], acc1[10], accb[10];
            #pragma unroll
            for (int k=0;k<10;k++){ acc0[k]=0.f; acc1[k]=0.f; accb[k]=0.f; }
            for (int j = jb[net]; j < je[net]; j++) {
                const float* f = sFeat + (bl*64 + i*8 + j)*10;
                float fr[10];
                #pragma unroll
                for (int k=0;k<10;k++) fr[k]=f[k];
                float h0 = b1[2*l], h1 = b1[2*l+1];
                #pragma unroll
                for (int k=0;k<9;k++){
                    h0 = fmaf(fr[k], w1[k*64+2*l],   h0);
                    h1 = fmaf(fr[k], w1[k*64+2*l+1], h1);
                }
                h0 = (h0>0.f)? h0 : 0.01f*h0;
                h1 = (h1>0.f)? h1 : 0.01f*h1;
                #pragma unroll
                for (int k=0;k<10;k++){
                    acc0[k] = fmaf(h0, fr[k], acc0[k]);
                    acc1[k] = fmaf(h1, fr[k], acc1[k]);
                    accb[k] += fr[k];
                }
            }
            float* gr = Gs + r*KPAD;
            #pragma unroll
            for (int k=0;k<10;k++){
                gr[(2*l)*10 + k]   = acc0[k];
                gr[(2*l+1)*10 + k] = acc1[k];
            }
            if (l == 0){
                #pragma unroll
                for (int k=0;k<10;k++) gr[640+k] = accb[k];
            }
        }
        // zero pad K=650..671
        for (int idx = t; idx < 16*22; idx += 128) {
            int r = idx / 22, c = 650 + idx % 22;
            Gs[r*KPAD + c] = 0.f;
        }
        __syncthreads();

        // ---- GEMM: accumulate Gs @ Mred[net] ----
        for (int k0 = 0; k0 < KPAD; k0 += 32) {
            const float4* msrc = (const float4*)(g_Mred + (net*KPAD + k0)*64);
            float4* md = (float4*)Ms;
            #pragma unroll
            for (int it=0; it<4; it++) md[t + it*128] = msrc[t + it*128];
            __syncthreads();
            #pragma unroll
            for (int kk=0; kk<32; kk++){
                float g0 = Gs[ty*KPAD + k0 + kk];
                float g1 = Gs[(ty+8)*KPAD + k0 + kk];
                float4 m = *(const float4*)(Ms + kk*64 + tx*4);
                a00=fmaf(g0,m.x,a00); a01=fmaf(g0,m.y,a01); a02=fmaf(g0,m.z,a02); a03=fmaf(g0,m.w,a03);
                a10=fmaf(g1,m.x,a10); a11=fmaf(g1,m.y,a11); a12=fmaf(g1,m.z,a12); a13=fmaf(g1,m.w,a13);
            }
            __syncthreads();
        }
        // trailing sync of last chunk also protects Gs rebuild next net
    }

    // ---- epilogue: reuse Gs as sX[16][68] ----
    float* sX = Gs;
    {
        int base0 = ty*68 + tx*4;
        sX[base0+0]=fmaxf(a00,0.f); sX[base0+1]=fmaxf(a01,0.f);
        sX[base0+2]=fmaxf(a02,0.f); sX[base0+3]=fmaxf(a03,0.f);
        int base1 = (ty+8)*68 + tx*4;
        sX[base1+0]=fmaxf(a10,0.f); sX[base1+1]=fmaxf(a11,0.f);
        sX[base1+2]=fmaxf(a12,0.f); sX[base1+3]=fmaxf(a13,0.f);
    }
    if (t < 48) {
        int r = t / 3, cc = t % 3;
        int bl = r >> 3, i = r & 7;
        float v;
        if (cc == 0) v = s_act[bl*3+0];
        else {
            float sb = s_act[bl*3+1], cb = s_act[bl*3+2];
            float si = s_sint[bl*8+i], ci = s_cost[bl*8+i];
            v = (cc == 1) ? (sb*ci - cb*si) : (cb*ci + sb*si);
        }
        sX[r*68 + 64 + cc] = fmaxf(v, 0.f);
    }
    __syncthreads();

    // ---- fc1 + fc2: warp w handles rows w, w+4, w+8, w+12; lane l cols l, l+32
    float fb0 = fc1b[l], fb1 = fc1b[l+32];
    float w20 = fc2w[l], w21 = fc2w[l+32];
    #pragma unroll
    for (int r4 = 0; r4 < 4; r4++) {
        int r = w + r4*4;
        const float* xr = sX + r*68;
        float v0 = fb0, v1 = fb1;
        #pragma unroll
        for (int c = 0; c < 67; c++) {
            float xv = xr[c];
            v0 = fmaf(xv, sF[c*64 + l],      v0);
            v1 = fmaf(xv, sF[c*64 + l + 32], v1);
        }
        v0 = fmaxf(v0, 0.f);
        v1 = fmaxf(v1, 0.f);
        int rowg = blockIdx.x*16 + r;
        out[NBA + rowg*64 + l]      = v0;
        out[NBA + rowg*64 + l + 32] = v1;
        float qp = v0*w20 + v1*w21;
        #pragma unroll
        for (int off=16; off; off>>=1) qp += __shfl_down_sync(0xffffffffu, qp, off);
        if (l == 0) s_q[r] = qp;
    }
    __syncthreads();
    if (t < 2) {
        float s = 0.f;
        #pragma unroll
        for (int k=0;k<8;k++) s += s_q[t*8+k];
        out[ba0 + t] = s*0.125f + fc2b[0];
    }
}

// ---------------- launch ----------------
extern "C" void kernel_launch(void* const* d_in, const int* in_sizes, int n_in,
                              void* d_out, int out_size) {
    const float* inputs = (const float*)d_in[0];
    const float* actions = (const float*)d_in[2];
    const float* hA1w=(const float*)d_in[3],  *hA1b=(const float*)d_in[4];
    const float* hA2w=(const float*)d_in[5],  *hA2b=(const float*)d_in[6];
    const float* hE1w=(const float*)d_in[7],  *hE1b=(const float*)d_in[8];
    const float* hE2w=(const float*)d_in[9],  *hE2b=(const float*)d_in[10];
    const float* hL1w=(const float*)d_in[11], *hL1b=(const float*)d_in[12];
    const float* hL2w=(const float*)d_in[13], *hL2b=(const float*)d_in[14];
    const float* mergw=(const float*)d_in[15];
    const float* fc1w=(const float*)d_in[16], *fc1b=(const float*)d_in[17];
    const float* fc2w=(const float*)d_in[18], *fc2b=(const float*)d_in[19];
    float* out = (float*)d_out;

    // floats: Gs 10752 + Ms 2048 + sF 4288 + sW1 1728 + sB1 192 + sFeat 1280 + scal 168
    const int smem_bytes = (10752 + 2048 + 4288 + 1728 + 192 + 1280 + 168) * 4;
    cudaFuncSetAttribute(k_fused, cudaFuncAttributeMaxDynamicSharedMemorySize, smem_bytes);

    dim3 g0(KPAD, 3);
    k_mred<<<g0, 64>>>(hA2w,hA2b,hE2w,hE2b,hL2w,hL2b,mergw);
    k_fused<<<192, 128, smem_bytes>>>(inputs, actions,
                                      hA1w,hA1b,hE1w,hE1b,hL1w,hL1b,
                                      fc1w,fc1b,fc2w,fc2b, out);
}

// round 5
// speedup vs baseline: 2.5709x; 1.3200x over previous
#include <cuda_runtime.h>
#include <math.h>

// ---------------------------------------------------------------------------
// RDHAgent forward. R5: grid 128, block 384 = 3 net-groups x 128 threads,
// 3 ba (24 rows) per block. Each net-group builds Gs[24][673] for its net and
// GEMMs vs Mred[net] (LDG from L2, no Ms staging), thread tile 3x8, 2-way
// K-split. Partials + epilogue reduced in shared (Gs reused).
// ---------------------------------------------------------------------------

#define NBA   384
#define KNET  650
#define KPAD  672
#define GPITCH 673         // Gs row pitch (odd -> conflict-free column reads)

__device__ float g_Mred[3 * KPAD * 64];

// ---------------- K0: build Mred[net][K][dh] ----------------
__global__ void k_mred(const float* __restrict__ wA2, const float* __restrict__ bA2,
                       const float* __restrict__ wE2, const float* __restrict__ bE2,
                       const float* __restrict__ wL2, const float* __restrict__ bL2,
                       const float* __restrict__ mergw) {
    int K = blockIdx.x, net = blockIdx.y, dh = threadIdx.x;
    float outv = 0.f;
    if (K < KNET) {
        float m0 = mergw[dh], m1 = mergw[64+dh], m2 = mergw[128+dh], m3 = mergw[192+dh];
        float mx = fmaxf(fmaxf(m0,m1), fmaxf(m2,m3));
        float e0 = expf(m0-mx), e1 = expf(m1-mx), e2 = expf(m2-mx), e3 = expf(m3-mx);
        float inv = 1.f/(e0+e1+e2+e3);
        int j10 = K/10;
        int k   = K - j10*10;
        const float* w2 = (net==0)?wA2:((net==1)?wE2:wL2);
        const float* b2 = (net==0)?bA2:((net==1)?bE2:bL2);
        const float* src = (j10 < 64) ? (w2 + j10*2560) : b2;
        int base = k*256 + dh;
        outv = (e0*src[base] + e1*src[base+64] + e2*src[base+128] + e3*src[base+192]) * inv;
    }
    g_Mred[(net*KPAD + K)*64 + dh] = outv;
}

// ---------------- K1: fused ----------------
// Shared (floats):
//   Gs[3][24][673] = 48456   (reused in epilogue: sP[6][24][64]=9216 @0,
//                             sX[24][68]=1632 @9216, sF[67*64]=4288 @10880)
//   sW1 [3][576]   = 1728    @48456
//   sB1 [3][64]    =  192    @50184
//   sFeat[3][64][10]= 1920   @50376
//   scalars (velx..rbf,act,q) ~249 @52296
__global__ void __launch_bounds__(384, 1) k_fused(
    const float* __restrict__ obs, const float* __restrict__ acts,
    const float* __restrict__ wA1, const float* __restrict__ bA1,
    const float* __restrict__ wE1, const float* __restrict__ bE1,
    const float* __restrict__ wL1, const float* __restrict__ bL1,
    const float* __restrict__ fc1w, const float* __restrict__ fc1b,
    const float* __restrict__ fc2w, const float* __restrict__ fc2b,
    float* __restrict__ out)
{
    extern __shared__ float sm[];
    float* Gs    = sm;                   // 48456
    float* sW1   = sm + 48456;           // 1728
    float* sB1   = sm + 50184;           // 192
    float* sFeat = sm + 50376;           // 1920
    float* sS    = sm + 52296;
    float* s_velx = sS;        // [24]
    float* s_vely = sS + 24;
    float* s_sint = sS + 48;
    float* s_cost = sS + 72;
    float* s_sina = sS + 96;
    float* s_cosa = sS + 120;
    float* s_rbf  = sS + 144;  // [24][3]
    float* s_act  = sS + 216;  // [3][3]
    float* s_q    = sS + 228;  // [24]

    const int t   = threadIdx.x;
    const int g   = t >> 7;            // net group 0..2
    const int tg  = t & 127;
    const int ba0 = blockIdx.x * 3;

    // ---- stage W1/b1 ----
    for (int idx = t; idx < 576; idx += 384) {
        sW1[idx] = wA1[idx]; sW1[576+idx] = wE1[idx]; sW1[1152+idx] = wL1[idx];
    }
    if (t < 192) {
        int n = t >> 6, c = t & 63;
        sB1[n*64+c] = (n==0)?bA1[c]:((n==1)?bE1[c]:bL1[c]);
    }

    // ---- per-entity scalars (24 = 3 ba x 8 entities) ----
    if (t < 24) {
        int bl = t >> 3, j = t & 7;
        const float* ob = obs + (ba0 + bl)*30;
        float px,py,vx,vy;
        if (j < 2)      { px=ob[10+2*j];     py=ob[11+2*j];     vx=ob[20+2*j];     vy=ob[21+2*j]; }
        else if (j < 5) { px=ob[14+2*(j-2)]; py=ob[15+2*(j-2)]; vx=ob[24+2*(j-2)]; vy=ob[25+2*(j-2)]; }
        else            { px=ob[4+2*(j-5)];  py=ob[5+2*(j-5)];  vx=-ob[0];         vy=-ob[1]; }
        float dist = sqrtf(px*px+py*py);
        float id = 1.f/(dist+1e-7f);
        s_sint[t]=py*id; s_cost[t]=px*id;
        float vn = sqrtf(vx*vx+vy*vy);
        float iv = 1.f/(vn+1e-7f);
        s_sina[t]=vy*iv; s_cosa[t]=vx*iv;
        s_velx[t]=vx; s_vely[t]=vy;
        s_rbf[t*3+0]=expf(-0.02f*dist*dist);
        float d1=dist-5.f;  s_rbf[t*3+1]=expf(-0.02f*d1*d1);
        float d2=dist-10.f; s_rbf[t*3+2]=expf(-0.02f*d2*d2);
    } else if (t < 27) {
        int bl = t - 24;
        float ax = acts[(ba0+bl)*2], ay = acts[(ba0+bl)*2+1];
        float an = sqrtf(ax*ax+ay*ay);
        s_act[bl*3+0]=an; s_act[bl*3+1]=ay/(an+1e-7f); s_act[bl*3+2]=ax/(an+1e-7f);
    }
    __syncthreads();

    // ---- feat'[10] per (bl,i,j) ----
    if (t < 192) {
        int bl = t >> 6, i = (t >> 3) & 7, j = t & 7;
        int oI = bl*8 + i, oJ = bl*8 + j;
        float* fd = sFeat + t*10;
        fd[0] = s_rbf[oJ*3+0];
        fd[1] = s_rbf[oJ*3+1];
        fd[2] = s_rbf[oJ*3+2];
        float si=s_sint[oI], ci=s_cost[oI], sj=s_sint[oJ], cj=s_cost[oJ];
        float sa=s_sina[oJ], ca=s_cosa[oJ];
        fd[3] = sj*ci - cj*si;
        fd[4] = cj*ci + sj*si;
        fd[5] = sa*ci - ca*si;
        fd[6] = ca*ci + sa*si;
        fd[7] = s_velx[oJ]-s_velx[oI];
        fd[8] = s_vely[oJ]-s_vely[oI];
        fd[9] = 1.f;
    }
    __syncthreads();

    // ---- build Gs for net g : 4 warps x 6 rows ----
    {
        const int wg = tg >> 5, l = tg & 31;
        const float* w1 = sW1 + g*576;
        const float* b1 = sB1 + g*64;
        float* Gn = Gs + g*24*GPITCH;
        const int jb = (g==0)?0:((g==1)?2:5);
        const int je = (g==0)?2:((g==1)?5:8);
        #pragma unroll
        for (int rr = 0; rr < 6; rr++) {
            int r  = wg*6 + rr;
            int bl = r >> 3, i = r & 7;
            float acc0[10], acc1[10], accb[10];
            #pragma unroll
            for (int k=0;k<10;k++){ acc0[k]=0.f; acc1[k]=0.f; accb[k]=0.f; }
            for (int j = jb; j < je; j++) {
                const float* f = sFeat + (bl*64 + i*8 + j)*10;
                float fr[10];
                #pragma unroll
                for (int k=0;k<10;k++) fr[k]=f[k];
                float h0 = b1[2*l], h1 = b1[2*l+1];
                #pragma unroll
                for (int k=0;k<9;k++){
                    h0 = fmaf(fr[k], w1[k*64+2*l],   h0);
                    h1 = fmaf(fr[k], w1[k*64+2*l+1], h1);
                }
                h0 = (h0>0.f)? h0 : 0.01f*h0;
                h1 = (h1>0.f)? h1 : 0.01f*h1;
                #pragma unroll
                for (int k=0;k<10;k++){
                    acc0[k] = fmaf(h0, fr[k], acc0[k]);
                    acc1[k] = fmaf(h1, fr[k], acc1[k]);
                    accb[k] += fr[k];
                }
            }
            float* gr = Gn + r*GPITCH;
            #pragma unroll
            for (int k=0;k<10;k++){
                gr[(2*l)*10 + k]   = acc0[k];
                gr[(2*l+1)*10 + k] = acc1[k];
            }
            if (l == 0){
                #pragma unroll
                for (int k=0;k<10;k++) gr[640+k] = accb[k];
            }
        }
    }
    // zero pad K=650..671 for all nets/rows
    for (int idx = t; idx < 3*24*22; idx += 384) {
        int n = idx / (24*22), rem = idx - n*24*22;
        int r = rem / 22, c = 650 + rem % 22;
        Gs[(n*24 + r)*GPITCH + c] = 0.f;
    }
    __syncthreads();

    // ---- GEMM: 24 x 64 x 672 per net, thread tile 3 rows x 8 cols ----
    const int half = (tg >> 6) & 1;
    const int t64  = tg & 63;
    const int rg   = t64 >> 3;      // 0..7 -> rows 3rg..3rg+2
    const int cg   = t64 & 7;       // cols 8cg..8cg+7
    float acc[3][8];
    #pragma unroll
    for (int a=0;a<3;a++)
        #pragma unroll
        for (int b=0;b<8;b++) acc[a][b]=0.f;
    {
        const float* Gn  = Gs + g*24*GPITCH;
        const float* gr0 = Gn + (3*rg+0)*GPITCH;
        const float* gr1 = Gn + (3*rg+1)*GPITCH;
        const float* gr2 = Gn + (3*rg+2)*GPITCH;
        const float4* Mv = (const float4*)(g_Mred + g*KPAD*64) + cg*2;
        const int k_beg = half ? 352 : 0;
        const int k_end = half ? 672 : 352;
        #pragma unroll 4
        for (int k = k_beg; k < k_end; k++) {
            float4 ma = Mv[k*16];
            float4 mb = Mv[k*16 + 1];
            float g0 = gr0[k], g1 = gr1[k], g2 = gr2[k];
            acc[0][0]=fmaf(g0,ma.x,acc[0][0]); acc[0][1]=fmaf(g0,ma.y,acc[0][1]);
            acc[0][2]=fmaf(g0,ma.z,acc[0][2]); acc[0][3]=fmaf(g0,ma.w,acc[0][3]);
            acc[0][4]=fmaf(g0,mb.x,acc[0][4]); acc[0][5]=fmaf(g0,mb.y,acc[0][5]);
            acc[0][6]=fmaf(g0,mb.z,acc[0][6]); acc[0][7]=fmaf(g0,mb.w,acc[0][7]);
            acc[1][0]=fmaf(g1,ma.x,acc[1][0]); acc[1][1]=fmaf(g1,ma.y,acc[1][1]);
            acc[1][2]=fmaf(g1,ma.z,acc[1][2]); acc[1][3]=fmaf(g1,ma.w,acc[1][3]);
            acc[1][4]=fmaf(g1,mb.x,acc[1][4]); acc[1][5]=fmaf(g1,mb.y,acc[1][5]);
            acc[1][6]=fmaf(g1,mb.z,acc[1][6]); acc[1][7]=fmaf(g1,mb.w,acc[1][7]);
            acc[2][0]=fmaf(g2,ma.x,acc[2][0]); acc[2][1]=fmaf(g2,ma.y,acc[2][1]);
            acc[2][2]=fmaf(g2,ma.z,acc[2][2]); acc[2][3]=fmaf(g2,ma.w,acc[2][3]);
            acc[2][4]=fmaf(g2,mb.x,acc[2][4]); acc[2][5]=fmaf(g2,mb.y,acc[2][5]);
            acc[2][6]=fmaf(g2,mb.z,acc[2][6]); acc[2][7]=fmaf(g2,mb.w,acc[2][7]);
        }
    }
    __syncthreads();   // Gs reads complete before overwrite

    // ---- reduce partials (reuse Gs) ----
    float* sP = Gs;                 // [6][24][64]
    const int g2 = t >> 6;          // 0..5 == g*2 + half
    #pragma unroll
    for (int a=0;a<3;a++){
        float* dst = sP + g2*1536 + (3*rg+a)*64 + cg*8;
        #pragma unroll
        for (int b=0;b<8;b++) dst[b] = acc[a][b];
    }
    __syncthreads();

    float* sX = Gs + 9216;          // [24][68]
    for (int idx = t; idx < 1536; idx += 384) {
        float v = sP[idx] + sP[1536+idx] + sP[3072+idx]
                + sP[4608+idx] + sP[6144+idx] + sP[7680+idx];
        int r = idx >> 6, c = idx & 63;
        sX[r*68 + c] = fmaxf(v, 0.f);
    }
    if (t < 72) {
        int r = t / 3, cc = t % 3;
        int bl = r >> 3, i = r & 7;
        float v;
        if (cc == 0) v = s_act[bl*3+0];
        else {
            float sb = s_act[bl*3+1], cb = s_act[bl*3+2];
            float si = s_sint[bl*8+i], ci = s_cost[bl*8+i];
            v = (cc == 1) ? (sb*ci - cb*si) : (cb*ci + sb*si);
        }
        sX[r*68 + 64 + cc] = fmaxf(v, 0.f);
    }
    float* sF = Gs + 10880;         // fc1w [67][64]
    for (int idx = t; idx < 4288; idx += 384) sF[idx] = fc1w[idx];
    __syncthreads();

    // ---- fc1 + fc2 : 12 warps, warp w -> rows 2w, 2w+1 ----
    const int w = t >> 5, l = t & 31;
    float fb0 = fc1b[l], fb1 = fc1b[l+32];
    float w20 = fc2w[l], w21 = fc2w[l+32];
    #pragma unroll
    for (int rr = 0; rr < 2; rr++) {
        int r = w*2 + rr;
        const float* xr = sX + r*68;
        float v0 = fb0, v1 = fb1;
        #pragma unroll
        for (int c = 0; c < 67; c++) {
            float xv = xr[c];
            v0 = fmaf(xv, sF[c*64 + l],      v0);
            v1 = fmaf(xv, sF[c*64 + l + 32], v1);
        }
        v0 = fmaxf(v0, 0.f);
        v1 = fmaxf(v1, 0.f);
        int rowg = ba0*8 + r;
        out[NBA + rowg*64 + l]      = v0;
        out[NBA + rowg*64 + l + 32] = v1;
        float qp = v0*w20 + v1*w21;
        #pragma unroll
        for (int off=16; off; off>>=1) qp += __shfl_down_sync(0xffffffffu, qp, off);
        if (l == 0) s_q[r] = qp;
    }
    __syncthreads();
    if (t < 3) {
        float s = 0.f;
        #pragma unroll
        for (int k=0;k<8;k++) s += s_q[t*8+k];
        out[ba0 + t] = s*0.125f + fc2b[0];
    }
}

// ---------------- launch ----------------
extern "C" void kernel_launch(void* const* d_in, const int* in_sizes, int n_in,
                              void* d_out, int out_size) {
    const float* inputs = (const float*)d_in[0];
    const float* actions = (const float*)d_in[2];
    const float* hA1w=(const float*)d_in[3],  *hA1b=(const float*)d_in[4];
    const float* hA2w=(const float*)d_in[5],  *hA2b=(const float*)d_in[6];
    const float* hE1w=(const float*)d_in[7],  *hE1b=(const float*)d_in[8];
    const float* hE2w=(const float*)d_in[9],  *hE2b=(const float*)d_in[10];
    const float* hL1w=(const float*)d_in[11], *hL1b=(const float*)d_in[12];
    const float* hL2w=(const float*)d_in[13], *hL2b=(const float*)d_in[14];
    const float* mergw=(const float*)d_in[15];
    const float* fc1w=(const float*)d_in[16], *fc1b=(const float*)d_in[17];
    const float* fc2w=(const float*)d_in[18], *fc2b=(const float*)d_in[19];
    float* out = (float*)d_out;

    // floats: Gs 48456 + sW1 1728 + sB1 192 + sFeat 1920 + scalars 252
    const int smem_bytes = (48456 + 1728 + 192 + 1920 + 252) * 4;   // 210192 B
    cudaFuncSetAttribute(k_fused, cudaFuncAttributeMaxDynamicSharedMemorySize, smem_bytes);

    dim3 g0(KPAD, 3);
    k_mred<<<g0, 64>>>(hA2w,hA2b,hE2w,hE2b,hL2w,hL2b,mergw);
    k_fused<<<128, 384, smem_bytes>>>(inputs, actions,
                                      hA1w,hA1b,hE1w,hE1b,hL1w,hL1b,
                                      fc1w,fc1b,fc2w,fc2b, out);
}

// round 6
// speedup vs baseline: 3.8120x; 1.4828x over previous
#include <cuda_runtime.h>
#include <math.h>

// ---------------------------------------------------------------------------
// RDHAgent forward. R6: R5 structure, GEMM micro-kernel reworked:
//   thread tile 6 rows x 8 cols, K-split 4, k vectorized by 4 (LDS.128 G,
//   double-buffered LDG.128 Mred). Gs pitch 676 for 16B alignment.
// ---------------------------------------------------------------------------

#define NBA   384
#define KNET  650
#define KPAD  672
#define GPITCH 676         // divisible by 4 (float4), bank offset 24/row

__device__ float g_Mred[3 * KPAD * 64];

// ---------------- K0: build Mred[net][K][dh] ----------------
__global__ void k_mred(const float* __restrict__ wA2, const float* __restrict__ bA2,
                       const float* __restrict__ wE2, const float* __restrict__ bE2,
                       const float* __restrict__ wL2, const float* __restrict__ bL2,
                       const float* __restrict__ mergw) {
    int K = blockIdx.x, net = blockIdx.y, dh = threadIdx.x;
    float outv = 0.f;
    if (K < KNET) {
        float m0 = mergw[dh], m1 = mergw[64+dh], m2 = mergw[128+dh], m3 = mergw[192+dh];
        float mx = fmaxf(fmaxf(m0,m1), fmaxf(m2,m3));
        float e0 = expf(m0-mx), e1 = expf(m1-mx), e2 = expf(m2-mx), e3 = expf(m3-mx);
        float inv = 1.f/(e0+e1+e2+e3);
        int j10 = K/10;
        int k   = K - j10*10;
        const float* w2 = (net==0)?wA2:((net==1)?wE2:wL2);
        const float* b2 = (net==0)?bA2:((net==1)?bE2:bL2);
        const float* src = (j10 < 64) ? (w2 + j10*2560) : b2;
        int base = k*256 + dh;
        outv = (e0*src[base] + e1*src[base+64] + e2*src[base+128] + e3*src[base+192]) * inv;
    }
    g_Mred[(net*KPAD + K)*64 + dh] = outv;
}

// ---------------- K1: fused ----------------
__global__ void __launch_bounds__(384, 1) k_fused(
    const float* __restrict__ obs, const float* __restrict__ acts,
    const float* __restrict__ wA1, const float* __restrict__ bA1,
    const float* __restrict__ wE1, const float* __restrict__ bE1,
    const float* __restrict__ wL1, const float* __restrict__ bL1,
    const float* __restrict__ fc1w, const float* __restrict__ fc1b,
    const float* __restrict__ fc2w, const float* __restrict__ fc2b,
    float* __restrict__ out)
{
    extern __shared__ float sm[];
    float* Gs    = sm;                       // 3*24*676 = 48672
    float* sW1   = sm + 48672;               // 1728
    float* sB1   = sm + 50400;               // 192
    float* sFeat = sm + 50592;               // 1920
    float* sS    = sm + 52512;
    float* s_velx = sS;        // [24]
    float* s_vely = sS + 24;
    float* s_sint = sS + 48;
    float* s_cost = sS + 72;
    float* s_sina = sS + 96;
    float* s_cosa = sS + 120;
    float* s_rbf  = sS + 144;  // [24][3]
    float* s_act  = sS + 216;  // [3][3]
    float* s_q    = sS + 228;  // [24]

    const int t   = threadIdx.x;
    const int g   = t >> 7;            // net group 0..2
    const int tg  = t & 127;
    const int ba0 = blockIdx.x * 3;

    // ---- stage W1/b1 ----
    for (int idx = t; idx < 576; idx += 384) {
        sW1[idx] = wA1[idx]; sW1[576+idx] = wE1[idx]; sW1[1152+idx] = wL1[idx];
    }
    if (t < 192) {
        int n = t >> 6, c = t & 63;
        sB1[n*64+c] = (n==0)?bA1[c]:((n==1)?bE1[c]:bL1[c]);
    }

    // ---- per-entity scalars ----
    if (t < 24) {
        int bl = t >> 3, j = t & 7;
        const float* ob = obs + (ba0 + bl)*30;
        float px,py,vx,vy;
        if (j < 2)      { px=ob[10+2*j];     py=ob[11+2*j];     vx=ob[20+2*j];     vy=ob[21+2*j]; }
        else if (j < 5) { px=ob[14+2*(j-2)]; py=ob[15+2*(j-2)]; vx=ob[24+2*(j-2)]; vy=ob[25+2*(j-2)]; }
        else            { px=ob[4+2*(j-5)];  py=ob[5+2*(j-5)];  vx=-ob[0];         vy=-ob[1]; }
        float dist = sqrtf(px*px+py*py);
        float id = 1.f/(dist+1e-7f);
        s_sint[t]=py*id; s_cost[t]=px*id;
        float vn = sqrtf(vx*vx+vy*vy);
        float iv = 1.f/(vn+1e-7f);
        s_sina[t]=vy*iv; s_cosa[t]=vx*iv;
        s_velx[t]=vx; s_vely[t]=vy;
        s_rbf[t*3+0]=expf(-0.02f*dist*dist);
        float d1=dist-5.f;  s_rbf[t*3+1]=expf(-0.02f*d1*d1);
        float d2=dist-10.f; s_rbf[t*3+2]=expf(-0.02f*d2*d2);
    } else if (t < 27) {
        int bl = t - 24;
        float ax = acts[(ba0+bl)*2], ay = acts[(ba0+bl)*2+1];
        float an = sqrtf(ax*ax+ay*ay);
        s_act[bl*3+0]=an; s_act[bl*3+1]=ay/(an+1e-7f); s_act[bl*3+2]=ax/(an+1e-7f);
    }
    __syncthreads();

    // ---- feat'[10] per (bl,i,j) ----
    if (t < 192) {
        int bl = t >> 6, i = (t >> 3) & 7, j = t & 7;
        int oI = bl*8 + i, oJ = bl*8 + j;
        float* fd = sFeat + t*10;
        fd[0] = s_rbf[oJ*3+0];
        fd[1] = s_rbf[oJ*3+1];
        fd[2] = s_rbf[oJ*3+2];
        float si=s_sint[oI], ci=s_cost[oI], sj=s_sint[oJ], cj=s_cost[oJ];
        float sa=s_sina[oJ], ca=s_cosa[oJ];
        fd[3] = sj*ci - cj*si;
        fd[4] = cj*ci + sj*si;
        fd[5] = sa*ci - ca*si;
        fd[6] = ca*ci + sa*si;
        fd[7] = s_velx[oJ]-s_velx[oI];
        fd[8] = s_vely[oJ]-s_vely[oI];
        fd[9] = 1.f;
    }
    __syncthreads();

    // ---- build Gs for net g : 4 warps x 6 rows ----
    {
        const int wg = tg >> 5, l = tg & 31;
        const float* w1 = sW1 + g*576;
        const float* b1 = sB1 + g*64;
        float* Gn = Gs + g*24*GPITCH;
        const int jb = (g==0)?0:((g==1)?2:5);
        const int je = (g==0)?2:((g==1)?5:8);
        #pragma unroll
        for (int rr = 0; rr < 6; rr++) {
            int r  = wg*6 + rr;
            int bl = r >> 3, i = r & 7;
            float acc0[10], acc1[10], accb[10];
            #pragma unroll
            for (int k=0;k<10;k++){ acc0[k]=0.f; acc1[k]=0.f; accb[k]=0.f; }
            for (int j = jb; j < je; j++) {
                const float* f = sFeat + (bl*64 + i*8 + j)*10;
                float fr[10];
                #pragma unroll
                for (int k=0;k<10;k++) fr[k]=f[k];
                float h0 = b1[2*l], h1 = b1[2*l+1];
                #pragma unroll
                for (int k=0;k<9;k++){
                    h0 = fmaf(fr[k], w1[k*64+2*l],   h0);
                    h1 = fmaf(fr[k], w1[k*64+2*l+1], h1);
                }
                h0 = (h0>0.f)? h0 : 0.01f*h0;
                h1 = (h1>0.f)? h1 : 0.01f*h1;
                #pragma unroll
                for (int k=0;k<10;k++){
                    acc0[k] = fmaf(h0, fr[k], acc0[k]);
                    acc1[k] = fmaf(h1, fr[k], acc1[k]);
                    accb[k] += fr[k];
                }
            }
            float* gr = Gn + r*GPITCH;
            #pragma unroll
            for (int k=0;k<10;k++){
                gr[(2*l)*10 + k]   = acc0[k];
                gr[(2*l+1)*10 + k] = acc1[k];
            }
            if (l == 0){
                #pragma unroll
                for (int k=0;k<10;k++) gr[640+k] = accb[k];
            }
        }
    }
    // zero pad K=650..675
    for (int idx = t; idx < 3*24*26; idx += 384) {
        int n = idx / (24*26), rem = idx - n*(24*26);
        int r = rem / 26, c = 650 + rem % 26;
        Gs[(n*24 + r)*GPITCH + c] = 0.f;
    }
    __syncthreads();

    // ---- GEMM: per net 24x64x672, thread tile 6x8, K-split 4, k-vec 4 ----
    const int ks   = tg >> 5;         // 0..3
    const int lane = tg & 31;
    const int rg   = lane >> 3;       // 0..3 -> rows 6rg..6rg+5
    const int cg   = lane & 7;        // cols 8cg..8cg+7
    const int k0   = ks * 168;

    float acc[6][8];
    #pragma unroll
    for (int a=0;a<6;a++)
        #pragma unroll
        for (int b=0;b<8;b++) acc[a][b]=0.f;
    {
        const float* Gbase = Gs + (g*24 + rg*6)*GPITCH;
        const float* Mk    = g_Mred + g*KPAD*64 + cg*8;   // + k*64

        float4 mc[4][2];
        #pragma unroll
        for (int kk=0; kk<4; kk++){
            mc[kk][0] = *(const float4*)(Mk + (k0+kk)*64);
            mc[kk][1] = *(const float4*)(Mk + (k0+kk)*64 + 4);
        }
        for (int kc = k0; kc < k0+168; kc += 4){
            // prefetch next chunk (last iter reloads current: harmless)
            int kn = (kc + 4 < k0+168) ? kc + 4 : kc;
            float4 mn[4][2];
            #pragma unroll
            for (int kk=0; kk<4; kk++){
                mn[kk][0] = *(const float4*)(Mk + (kn+kk)*64);
                mn[kk][1] = *(const float4*)(Mk + (kn+kk)*64 + 4);
            }
            float4 gv[6];
            #pragma unroll
            for (int r=0;r<6;r++)
                gv[r] = *(const float4*)(Gbase + r*GPITCH + kc);
            #pragma unroll
            for (int kk=0; kk<4; kk++){
                float m0=mc[kk][0].x, m1=mc[kk][0].y, m2=mc[kk][0].z, m3=mc[kk][0].w;
                float m4=mc[kk][1].x, m5=mc[kk][1].y, m6=mc[kk][1].z, m7=mc[kk][1].w;
                #pragma unroll
                for (int r=0;r<6;r++){
                    const float* gp = (const float*)&gv[r];
                    float gsv = gp[kk];
                    acc[r][0]=fmaf(gsv,m0,acc[r][0]); acc[r][1]=fmaf(gsv,m1,acc[r][1]);
                    acc[r][2]=fmaf(gsv,m2,acc[r][2]); acc[r][3]=fmaf(gsv,m3,acc[r][3]);
                    acc[r][4]=fmaf(gsv,m4,acc[r][4]); acc[r][5]=fmaf(gsv,m5,acc[r][5]);
                    acc[r][6]=fmaf(gsv,m6,acc[r][6]); acc[r][7]=fmaf(gsv,m7,acc[r][7]);
                }
            }
            #pragma unroll
            for (int kk=0; kk<4; kk++){ mc[kk][0]=mn[kk][0]; mc[kk][1]=mn[kk][1]; }
        }
    }
    __syncthreads();   // all Gs reads done before reuse

    // ---- write partials: slab = g*4+ks -> sP[12][24][64] ----
    float* sP = Gs;
    {
        float* base = sP + (g*4 + ks)*1536 + (rg*6)*64 + cg*8;
        #pragma unroll
        for (int r=0;r<6;r++){
            float4 o0; o0.x=acc[r][0]; o0.y=acc[r][1]; o0.z=acc[r][2]; o0.w=acc[r][3];
            float4 o1; o1.x=acc[r][4]; o1.y=acc[r][5]; o1.z=acc[r][6]; o1.w=acc[r][7];
            *(float4*)(base + r*64)     = o0;
            *(float4*)(base + r*64 + 4) = o1;
        }
    }
    __syncthreads();

    float* sX = Gs + 18432;          // [24][68]
    for (int idx = t; idx < 1536; idx += 384) {
        float v = 0.f;
        #pragma unroll
        for (int s=0;s<12;s++) v += sP[s*1536 + idx];
        int r = idx >> 6, c = idx & 63;
        sX[r*68 + c] = fmaxf(v, 0.f);
    }
    if (t < 72) {
        int r = t / 3, cc = t % 3;
        int bl = r >> 3, i = r & 7;
        float v;
        if (cc == 0) v = s_act[bl*3+0];
        else {
            float sb = s_act[bl*3+1], cb = s_act[bl*3+2];
            float si = s_sint[bl*8+i], ci = s_cost[bl*8+i];
            v = (cc == 1) ? (sb*ci - cb*si) : (cb*ci + sb*si);
        }
        sX[r*68 + 64 + cc] = fmaxf(v, 0.f);
    }
    float* sF = Gs + 20064;          // fc1w [67][64]
    for (int idx = t; idx < 4288; idx += 384) sF[idx] = fc1w[idx];
    __syncthreads();

    // ---- fc1 + fc2 : 12 warps, warp w -> rows 2w, 2w+1 ----
    const int w = t >> 5, l = t & 31;
    float fb0 = fc1b[l], fb1 = fc1b[l+32];
    float w20 = fc2w[l], w21 = fc2w[l+32];
    #pragma unroll
    for (int rr = 0; rr < 2; rr++) {
        int r = w*2 + rr;
        const float* xr = sX + r*68;
        float v0 = fb0, v1 = fb1;
        #pragma unroll
        for (int c = 0; c < 67; c++) {
            float xv = xr[c];
            v0 = fmaf(xv, sF[c*64 + l],      v0);
            v1 = fmaf(xv, sF[c*64 + l + 32], v1);
        }
        v0 = fmaxf(v0, 0.f);
        v1 = fmaxf(v1, 0.f);
        int rowg = ba0*8 + r;
        out[NBA + rowg*64 + l]      = v0;
        out[NBA + rowg*64 + l + 32] = v1;
        float qp = v0*w20 + v1*w21;
        #pragma unroll
        for (int off=16; off; off>>=1) qp += __shfl_down_sync(0xffffffffu, qp, off);
        if (l == 0) s_q[r] = qp;
    }
    __syncthreads();
    if (t < 3) {
        float s = 0.f;
        #pragma unroll
        for (int k=0;k<8;k++) s += s_q[t*8+k];
        out[ba0 + t] = s*0.125f + fc2b[0];
    }
}

// ---------------- launch ----------------
extern "C" void kernel_launch(void* const* d_in, const int* in_sizes, int n_in,
                              void* d_out, int out_size) {
    const float* inputs = (const float*)d_in[0];
    const float* actions = (const float*)d_in[2];
    const float* hA1w=(const float*)d_in[3],  *hA1b=(const float*)d_in[4];
    const float* hA2w=(const float*)d_in[5],  *hA2b=(const float*)d_in[6];
    const float* hE1w=(const float*)d_in[7],  *hE1b=(const float*)d_in[8];
    const float* hE2w=(const float*)d_in[9],  *hE2b=(const float*)d_in[10];
    const float* hL1w=(const float*)d_in[11], *hL1b=(const float*)d_in[12];
    const float* hL2w=(const float*)d_in[13], *hL2b=(const float*)d_in[14];
    const float* mergw=(const float*)d_in[15];
    const float* fc1w=(const float*)d_in[16], *fc1b=(const float*)d_in[17];
    const float* fc2w=(const float*)d_in[18], *fc2b=(const float*)d_in[19];
    float* out = (float*)d_out;

    // floats: Gs 48672 + sW1 1728 + sB1 192 + sFeat 1920 + scalars 252 = 52764
    const int smem_bytes = 52764 * 4;   // 211056 B
    cudaFuncSetAttribute(k_fused, cudaFuncAttributeMaxDynamicSharedMemorySize, smem_bytes);

    dim3 g0(KPAD, 3);
    k_mred<<<g0, 64>>>(hA2w,hA2b,hE2w,hE2b,hL2w,hL2b,mergw);
    k_fused<<<128, 384, smem_bytes>>>(inputs, actions,
                                      hA1w,hA1b,hE1w,hE1b,hL1w,hL1b,
                                      fc1w,fc1b,fc2w,fc2b, out);
}